// round 13
// baseline (speedup 1.0000x reference)
#include <cuda_runtime.h>
#include <cuda_fp16.h>
#include <math.h>
#include <stdint.h>

// Problem constants (fixed shapes from reference)
#define H 112
#define W 112
#define HW 12544
#define CIN 64
#define OUTC 64
#define NB 8
#define NOFF 27          // 3*K*K
#define KK 576           // CIN * 9

// Scratch (static __device__ — no runtime allocation)
__device__ __align__(16) uint16_t g_xt[NB * HW * CIN];   // x in NHWC fp16 [N][H][W][C]
__device__ __align__(16) uint16_t g_wtt[9 * 64 * 64];    // main weights [t][o][c], fp16
__device__ __align__(16) uint16_t g_owtt[9 * 32 * 64];   // offset weights [t][oc(pad32)][c], fp16

#define MMA_F16(d, a0, a1, a2, a3, b0, b1)                                    \
    asm volatile("mma.sync.aligned.m16n8k16.row.col.f32.f16.f16.f32 "         \
        "{%0,%1,%2,%3}, {%4,%5,%6,%7}, {%8,%9}, {%0,%1,%2,%3};"               \
        : "+f"((d)[0]), "+f"((d)[1]), "+f"((d)[2]), "+f"((d)[3])              \
        : "r"(a0), "r"(a1), "r"(a2), "r"(a3), "r"(b0), "r"(b1))

// pack 2 floats -> half2 bits
__device__ __forceinline__ uint32_t f2h2(float lo, float hi) {
    __half2 h = __floats2half2_rn(lo, hi);
    return *(uint32_t*)&h;
}

// ---------------------------------------------------------------------------
// Kernel 0 (merged prep): blocks [0,3136) NCHW f32 -> NHWC fp16;
//                         blocks [3136,3280) weight prep (fp16 layouts)
// ---------------------------------------------------------------------------
__global__ void k_prep(const float* __restrict__ x, const float* __restrict__ w,
                       const float* __restrict__ ow) {
    __shared__ float tile[64][33];
    const int bid = blockIdx.x, tid = threadIdx.x;
    if (bid < 3136) {
        const int n = bid / 392, p0 = (bid % 392) * 32;
        const float* xn = x + (size_t)n * CIN * HW;
        uint16_t* xtn = g_xt + (size_t)n * HW * CIN;
        const int tx = tid & 31, ty = tid >> 5;   // 32x8
        #pragma unroll
        for (int i = 0; i < 64; i += 8)
            tile[ty + i][tx] = xn[(size_t)(ty + i) * HW + p0 + tx];
        __syncthreads();
        const int p = tid >> 3, c8 = (tid & 7) * 8;
        uint4 u;
        u.x = f2h2(tile[c8 + 0][p], tile[c8 + 1][p]);
        u.y = f2h2(tile[c8 + 2][p], tile[c8 + 3][p]);
        u.z = f2h2(tile[c8 + 4][p], tile[c8 + 5][p]);
        u.w = f2h2(tile[c8 + 6][p], tile[c8 + 7][p]);
        *(uint4*)(xtn + (size_t)(p0 + p) * CIN + c8) = u;
    } else {
        int idx = (bid - 3136) * 256 + tid;       // 0..36863
        if (idx < 9 * 32 * 64) {
            int t = idx >> 11, oc = (idx >> 6) & 31, c = idx & 63;
            float v = (oc < NOFF) ? ow[oc * KK + c * 9 + t] : 0.f;
            __half h = __float2half_rn(v);
            g_owtt[idx] = *(uint16_t*)&h;
        }
        {
            int t = idx >> 12, o = (idx >> 6) & 63, c = idx & 63;
            float v = w[o * KK + c * 9 + t];
            __half h = __float2half_rn(v);
            g_wtt[idx] = *(uint16_t*)&h;
        }
    }
}

// ---------------------------------------------------------------------------
// Kernel 1 (fused, pipelined): offset conv + sampling + main GEMM.
// Tile: 16 wo x 4 ho = 64 px, 128 threads (4 warps), 5 CTAs/SM.
//
// SMEM (44032 B), fp16 row stride 72 halves = 144 B:
//   [0    ,18432) val double buffer [2][64][72]h | ph1: patch [108][72]h (15552)
//   [18432,36864) w   double buffer [2][64][72]h | ph1: owt [2][32][72]h @18432,
//                                                |      raw [64][28]f32 @27648
//   [36864,43776) pym [9][64][3] f32 (py, px, mask)
//   [43776,44032) bs  [64] f32
//
// Pipeline (both phases): iteration t stages buffers for t+1 (copy/gather),
// then MMAs tap t; ONE __syncthreads per tap.
// ---------------------------------------------------------------------------
__global__ void __launch_bounds__(128, 5)
k_main(const float* __restrict__ bias, const float* __restrict__ ob,
       float* __restrict__ out) {
    extern __shared__ unsigned char sm[];
    uint16_t* patch = (uint16_t*)sm;                 // [108][72] (phase 1)
    float*    raw_s = (float*)(sm + 27648);          // [64][28]  (inter-phase)
    float*    pym   = (float*)(sm + 36864);          // [9][64][3]
    float*    bs    = (float*)(sm + 43776);          // [64]

    const int tid = threadIdx.x;
    const int wo0 = blockIdx.x * 16, ho0 = blockIdx.y * 4, n = blockIdx.z;
    const int lane = tid & 31, warp = tid >> 5;
    const uint16_t* xtn = g_xt + (size_t)n * (HW * CIN);

    // mma lane mapping (shared by both phases)
    const int g = lane >> 2, ti = lane & 3;

    // bias -> smem (warps 2,3; no conflict with anything until epilogue)
    if (tid >= 64) bs[tid - 64] = bias[tid - 64];

    // ======================= PHASE 1: offset conv ==========================
    // patch copy: 108 pos x 8 groups (8 halves) = 864 tasks, pure uint4 copy
    for (int i = tid; i < 864; i += 128) {
        int pos = i >> 3, q8 = (i & 7) * 8;
        int gy = ho0 - 1 + pos / 18, gx = wo0 - 1 + pos % 18;
        uint4 u = make_uint4(0u, 0u, 0u, 0u);
        if (gy >= 0 && gy < H && gx >= 0 && gx < W)
            u = *(const uint4*)(xtn + (size_t)(gy * W + gx) * CIN + q8);
        *(uint4*)(patch + pos * 72 + q8) = u;
    }

    float aoff[4][4];
    #pragma unroll
    for (int j = 0; j < 4; j++)
        #pragma unroll
        for (int i = 0; i < 4; i++) aoff[j][i] = 0.f;

    auto owtcopy = [&](int tt, int p) {
        const float4* src = (const float4*)(g_owtt + tt * 2048);
        uint16_t* dst = (uint16_t*)(sm + 18432 + p * 4608);
        #pragma unroll
        for (int i = 0; i < 2; i++) {
            int q = tid + i * 128;                   // 0..255 (16B = 8 halves)
            float4 v = src[q];
            *(float4*)(dst + (q >> 3) * 72 + (q & 7) * 8) = v;
        }
    };
    auto mma_off = [&](int tt, int p) {
        const uint16_t* owt_h = (const uint16_t*)(sm + 18432 + p * 4608);
        const int base = (warp + tt / 3) * 18 + (tt % 3);
        #pragma unroll
        for (int s = 0; s < 4; s++) {
            const int ko = 16 * s + 2 * ti;
            const uint16_t* ap0 = patch + (base + g) * 72 + ko;
            const uint16_t* ap1 = patch + (base + g + 8) * 72 + ko;
            uint32_t a0 = *(const uint32_t*)ap0;
            uint32_t a2 = *(const uint32_t*)(ap0 + 8);
            uint32_t a1 = *(const uint32_t*)ap1;
            uint32_t a3 = *(const uint32_t*)(ap1 + 8);
            #pragma unroll
            for (int j = 0; j < 4; j++) {
                const uint16_t* bp = owt_h + (j * 8 + g) * 72 + ko;
                uint32_t b0 = *(const uint32_t*)bp;
                uint32_t b1 = *(const uint32_t*)(bp + 8);
                MMA_F16(aoff[j], a0, a1, a2, a3, b0, b1);
            }
        }
    };

    owtcopy(0, 0);
    __syncthreads();                                  // patch + owt(0) ready
    for (int t = 0; t < 9; t++) {
        if (t < 8) owtcopy(t + 1, (t + 1) & 1);
        mma_off(t, t & 1);
        __syncthreads();
    }

    // write raw_s[px][27] (+ offset bias); warp w owns px rows w*16+g, +8
    {
        const int r0 = warp * 16 + g, r1 = warp * 16 + 8 + g;
        #pragma unroll
        for (int j = 0; j < 4; j++) {
            int oc0 = 8 * j + 2 * ti;
            if (oc0 < NOFF) {
                float b = ob[oc0];
                raw_s[r0 * 28 + oc0] = aoff[j][0] + b;
                raw_s[r1 * 28 + oc0] = aoff[j][2] + b;
            }
            if (oc0 + 1 < NOFF) {
                float b = ob[oc0 + 1];
                raw_s[r0 * 28 + oc0 + 1] = aoff[j][1] + b;
                raw_s[r1 * 28 + oc0 + 1] = aoff[j][3] + b;
            }
        }
    }
    __syncthreads();

    // precompute (py, px, mask) for all 9 taps (expf once per tap here)
    if (tid < 64) {
        const int y = tid >> 4, wxl = tid & 15;
        const int ho = ho0 + y, wo = wo0 + wxl;
        #pragma unroll
        for (int t = 0; t < 9; t++) {
            float dyv = raw_s[tid * 28 + 2 * t];
            float dxv = raw_s[tid * 28 + 2 * t + 1];
            float mv  = raw_s[tid * 28 + 18 + t];
            float m = 1.f / (1.f + expf(-mv));
            float* pp = pym + (t * 64 + tid) * 3;
            pp[0] = dyv + (float)(ho - 1 + t / 3);
            pp[1] = dxv + (float)(wo - 1 + t % 3);
            pp[2] = m;
        }
    }
    __syncthreads();

    // ======================= PHASE 2: main conv ============================
    const int sub = lane >> 3;                  // 0..3 (4 px per pass)
    const int c8 = (lane & 7) * 8;              // 8 channels per lane
    const int px0 = (warp & 1) * 32;
    const int o0  = (warp >> 1) * 32;

    float acc[2][4][4];
    #pragma unroll
    for (int mt = 0; mt < 2; mt++)
        #pragma unroll
        for (int j = 0; j < 4; j++)
            #pragma unroll
            for (int i = 0; i < 4; i++) acc[mt][j][i] = 0.f;

    auto stage_ab = [&](int tt, int p) {
        // weights -> w buffer
        const float4* wsrc = (const float4*)(g_wtt + tt * 4096);
        uint16_t* wbuf = (uint16_t*)(sm + 18432 + p * 9216);
        #pragma unroll
        for (int i = 0; i < 4; i++) {
            int q = tid + i * 128;                   // 0..511 (16B = 8 halves)
            float4 v = wsrc[q];
            *(float4*)(wbuf + (q >> 3) * 72 + (q & 7) * 8) = v;
        }
        // gather with inline corner math
        uint16_t* vbuf = (uint16_t*)(sm + p * 9216);
        #pragma unroll
        for (int it = 0; it < 4; it++) {
            int px = warp * 16 + it * 4 + sub;       // 0..63
            const float* pp = pym + (tt * 64 + px) * 3;
            float py = pp[0], pxx = pp[1], m = pp[2];
            float y0f = floorf(py), x0f = floorf(pxx);
            float wy1 = py - y0f, wy0 = 1.f - wy1;
            float wx1 = pxx - x0f, wx0 = 1.f - wx1;
            int y0 = (int)y0f, x0 = (int)x0f;
            int y1 = y0 + 1, x1 = x0 + 1;
            bool vy0 = (y0 >= 0) && (y0 < H), vy1 = (y1 >= 0) && (y1 < H);
            bool vx0 = (x0 >= 0) && (x0 < W), vx1 = (x1 >= 0) && (x1 < W);
            float w00 = (vy0 && vx0) ? wy0 * wx0 * m : 0.f;
            float w01 = (vy0 && vx1) ? wy0 * wx1 * m : 0.f;
            float w10 = (vy1 && vx0) ? wy1 * wx0 * m : 0.f;
            float w11 = (vy1 && vx1) ? wy1 * wx1 * m : 0.f;
            int yc0 = min(max(y0, 0), H - 1), yc1 = min(max(y1, 0), H - 1);
            int xc0 = min(max(x0, 0), W - 1), xc1 = min(max(x1, 0), W - 1);
            int i0 = yc0 * W + xc0, i1 = yc0 * W + xc1;
            int i2 = yc1 * W + xc0, i3 = yc1 * W + xc1;
            uint4 q0 = *(const uint4*)(xtn + (size_t)i0 * CIN + c8);
            uint4 q1 = *(const uint4*)(xtn + (size_t)i1 * CIN + c8);
            uint4 q2 = *(const uint4*)(xtn + (size_t)i2 * CIN + c8);
            uint4 q3 = *(const uint4*)(xtn + (size_t)i3 * CIN + c8);
            uint4 r;
            uint32_t* rp = (uint32_t*)&r;
            const uint32_t* p0 = (const uint32_t*)&q0;
            const uint32_t* p1 = (const uint32_t*)&q1;
            const uint32_t* p2 = (const uint32_t*)&q2;
            const uint32_t* p3 = (const uint32_t*)&q3;
            #pragma unroll
            for (int j = 0; j < 4; j++) {
                float2 a = __half22float2(*(const __half2*)&p0[j]);
                float2 b = __half22float2(*(const __half2*)&p1[j]);
                float2 c = __half22float2(*(const __half2*)&p2[j]);
                float2 d = __half22float2(*(const __half2*)&p3[j]);
                float vx = fmaf(w11, d.x, fmaf(w10, c.x, fmaf(w01, b.x, w00 * a.x)));
                float vy = fmaf(w11, d.y, fmaf(w10, c.y, fmaf(w01, b.y, w00 * a.y)));
                rp[j] = f2h2(vx, vy);
            }
            *(uint4*)(vbuf + px * 72 + c8) = r;
        }
    };
    auto mma_main = [&](int p) {
        const uint16_t* vb = (const uint16_t*)(sm + p * 9216);
        const uint16_t* wb = (const uint16_t*)(sm + 18432 + p * 9216);
        #pragma unroll
        for (int s = 0; s < 4; s++) {
            const int ko = 16 * s + 2 * ti;
            #pragma unroll
            for (int mt = 0; mt < 2; mt++) {
                const uint16_t* ap0 = vb + (px0 + 16 * mt + g) * 72 + ko;
                const uint16_t* ap1 = vb + (px0 + 16 * mt + g + 8) * 72 + ko;
                uint32_t a0 = *(const uint32_t*)ap0;
                uint32_t a2 = *(const uint32_t*)(ap0 + 8);
                uint32_t a1 = *(const uint32_t*)ap1;
                uint32_t a3 = *(const uint32_t*)(ap1 + 8);
                #pragma unroll
                for (int j = 0; j < 4; j++) {
                    const uint16_t* bp = wb + (o0 + 8 * j + g) * 72 + ko;
                    uint32_t b0 = *(const uint32_t*)bp;
                    uint32_t b1 = *(const uint32_t*)(bp + 8);
                    MMA_F16(acc[mt][j], a0, a1, a2, a3, b0, b1);
                }
            }
        }
    };

    stage_ab(0, 0);
    __syncthreads();
    for (int t = 0; t < 9; t++) {
        if (t < 8) stage_ab(t + 1, (t + 1) & 1);    // overlaps mma(t)
        mma_main(t & 1);
        __syncthreads();
    }

    // ---- epilogue: D frags + bias -> out (NCHW) ----
    #pragma unroll
    for (int mt = 0; mt < 2; mt++) {
        const int ho = ho0 + 2 * (warp & 1) + mt;
        float* op = out + (((size_t)n * OUTC) * H + ho) * W + wo0;
        #pragma unroll
        for (int j = 0; j < 4; j++) {
            int oc = o0 + 8 * j + 2 * ti;
            float b0v = bs[oc], b1v = bs[oc + 1];
            op[(size_t)oc * HW + g]            = acc[mt][j][0] + b0v;
            op[(size_t)(oc + 1) * HW + g]      = acc[mt][j][1] + b1v;
            op[(size_t)oc * HW + g + 8]        = acc[mt][j][2] + b0v;
            op[(size_t)(oc + 1) * HW + g + 8]  = acc[mt][j][3] + b1v;
        }
    }
}

// ---------------------------------------------------------------------------
extern "C" void kernel_launch(void* const* d_in, const int* in_sizes, int n_in,
                              void* d_out, int out_size) {
    (void)in_sizes; (void)n_in; (void)out_size;
    const float* x        = (const float*)d_in[0];
    const float* weight   = (const float*)d_in[1];
    const float* bias     = (const float*)d_in[2];
    const float* offset_w = (const float*)d_in[3];
    const float* offset_b = (const float*)d_in[4];
    float* out = (float*)d_out;

    k_prep<<<3280, 256>>>(x, weight, offset_w);
    k_main<<<dim3(7, 28, 8), 128, 44032>>>(bias, offset_b, out);
}

// round 14
// speedup vs baseline: 1.1025x; 1.1025x over previous
#include <cuda_runtime.h>
#include <cuda_fp16.h>
#include <math.h>
#include <stdint.h>

// Problem constants (fixed shapes from reference)
#define H 112
#define W 112
#define HW 12544
#define CIN 64
#define OUTC 64
#define NB 8
#define NOFF 27          // 3*K*K
#define KK 576           // CIN * 9

// Scratch (static __device__ — no runtime allocation)
__device__ __align__(16) uint16_t g_xt[NB * HW * CIN];   // x in NHWC fp16 [N][H][W][C]
__device__ __align__(16) uint16_t g_wtt[9 * 64 * 64];    // main weights [t][o][c], fp16
__device__ __align__(16) uint16_t g_owtt[9 * 32 * 64];   // offset weights [t][oc(pad32)][c], fp16

#define MMA_F16(d, a0, a1, a2, a3, b0, b1)                                    \
    asm volatile("mma.sync.aligned.m16n8k16.row.col.f32.f16.f16.f32 "         \
        "{%0,%1,%2,%3}, {%4,%5,%6,%7}, {%8,%9}, {%0,%1,%2,%3};"               \
        : "+f"((d)[0]), "+f"((d)[1]), "+f"((d)[2]), "+f"((d)[3])              \
        : "r"(a0), "r"(a1), "r"(a2), "r"(a3), "r"(b0), "r"(b1))

#define LDSM_X4(r0, r1, r2, r3, a)                                            \
    asm volatile("ldmatrix.sync.aligned.m8n8.x4.shared.b16 {%0,%1,%2,%3}, [%4];" \
        : "=r"(r0), "=r"(r1), "=r"(r2), "=r"(r3) : "r"(a))

// pack 2 floats -> half2 bits
__device__ __forceinline__ uint32_t f2h2(float lo, float hi) {
    __half2 h = __floats2half2_rn(lo, hi);
    return *(uint32_t*)&h;
}
__device__ __forceinline__ uint32_t smem_u32(const void* p) {
    uint32_t a;
    asm("{ .reg .u64 t; cvta.to.shared.u64 t, %1; cvt.u32.u64 %0, t; }" : "=r"(a) : "l"(p));
    return a;
}

// ---------------------------------------------------------------------------
// Kernel 0 (merged prep): blocks [0,3136) NCHW f32 -> NHWC fp16;
//                         blocks [3136,3280) weight prep (fp16 layouts)
// ---------------------------------------------------------------------------
__global__ void k_prep(const float* __restrict__ x, const float* __restrict__ w,
                       const float* __restrict__ ow) {
    __shared__ float tile[64][33];
    const int bid = blockIdx.x, tid = threadIdx.x;
    if (bid < 3136) {
        const int n = bid / 392, p0 = (bid % 392) * 32;
        const float* xn = x + (size_t)n * CIN * HW;
        uint16_t* xtn = g_xt + (size_t)n * HW * CIN;
        const int tx = tid & 31, ty = tid >> 5;   // 32x8
        #pragma unroll
        for (int i = 0; i < 64; i += 8)
            tile[ty + i][tx] = xn[(size_t)(ty + i) * HW + p0 + tx];
        __syncthreads();
        const int p = tid >> 3, c8 = (tid & 7) * 8;
        uint4 u;
        u.x = f2h2(tile[c8 + 0][p], tile[c8 + 1][p]);
        u.y = f2h2(tile[c8 + 2][p], tile[c8 + 3][p]);
        u.z = f2h2(tile[c8 + 4][p], tile[c8 + 5][p]);
        u.w = f2h2(tile[c8 + 6][p], tile[c8 + 7][p]);
        *(uint4*)(xtn + (size_t)(p0 + p) * CIN + c8) = u;
    } else {
        int idx = (bid - 3136) * 256 + tid;       // 0..36863
        if (idx < 9 * 32 * 64) {
            int t = idx >> 11, oc = (idx >> 6) & 31, c = idx & 63;
            float v = (oc < NOFF) ? ow[oc * KK + c * 9 + t] : 0.f;
            __half h = __float2half_rn(v);
            g_owtt[idx] = *(uint16_t*)&h;
        }
        {
            int t = idx >> 12, o = (idx >> 6) & 63, c = idx & 63;
            float v = w[o * KK + c * 9 + t];
            __half h = __float2half_rn(v);
            g_wtt[idx] = *(uint16_t*)&h;
        }
    }
}

// ---------------------------------------------------------------------------
// Kernel 1 (fused): offset conv + deformable sampling + main GEMM.
// Tile: 16 wo x 4 ho = 64 px, 128 threads (4 warps), 6 CTAs/SM.
//
// SMEM (37376 B), fp16 row stride 72 halves = 144 B:
//   [0    , 9216) val_h [64][72]  | ph1: patch [108][72] (15552, spills to w_h)
//   [9216 ,18432) w_h   [64][72]  |
//   [18432,23040) owt_h [32][72]  (phase 1)
//   [23040,30208) raw_s [64][28] f32
//   [30208,37120) pym   [9][64][3] f32
//   [37120,37376) bs    [64] f32
//
// Stage C uses ldmatrix.x4 for A and B fragments (16 LDSM vs 64 LDS.b32).
// ---------------------------------------------------------------------------
__global__ void __launch_bounds__(128, 6)
k_main(const float* __restrict__ bias, const float* __restrict__ ob,
       float* __restrict__ out) {
    extern __shared__ unsigned char sm[];
    uint16_t* val_h = (uint16_t*)sm;                 // [64][72]
    uint16_t* w_h   = (uint16_t*)(sm + 9216);        // [64][72]
    uint16_t* patch = (uint16_t*)sm;                 // [108][72] (phase 1)
    uint16_t* owt_h = (uint16_t*)(sm + 18432);       // [32][72] (phase 1)
    float*    raw_s = (float*)(sm + 23040);          // [64][28]
    float*    pym   = (float*)(sm + 30208);          // [9][64][3]
    float*    bs    = (float*)(sm + 37120);          // [64]

    const int tid = threadIdx.x;
    const int wo0 = blockIdx.x * 16, ho0 = blockIdx.y * 4, n = blockIdx.z;
    const int lane = tid & 31, warp = tid >> 5;
    const uint16_t* xtn = g_xt + (size_t)n * (HW * CIN);

    // mma lane mapping
    const int g = lane >> 2, ti = lane & 3;
    // ldmatrix lane->address offsets
    const int a_row = lane & 15, a_col = (lane >> 4) << 3;
    const int b_row = ((lane >> 4) << 3) + (lane & 7), b_col = ((lane >> 3) & 1) << 3;

    if (tid >= 64) bs[tid - 64] = bias[tid - 64];

    // ======================= PHASE 1: offset conv ==========================
    for (int i = tid; i < 864; i += 128) {
        int pos = i >> 3, q8 = (i & 7) * 8;
        int gy = ho0 - 1 + pos / 18, gx = wo0 - 1 + pos % 18;
        uint4 u = make_uint4(0u, 0u, 0u, 0u);
        if (gy >= 0 && gy < H && gx >= 0 && gx < W)
            u = *(const uint4*)(xtn + (size_t)(gy * W + gx) * CIN + q8);
        *(uint4*)(patch + pos * 72 + q8) = u;
    }

    float aoff[4][4];
    #pragma unroll
    for (int j = 0; j < 4; j++)
        #pragma unroll
        for (int i = 0; i < 4; i++) aoff[j][i] = 0.f;

    for (int t = 0; t < 9; t++) {
        // owt tile t -> owt_h [32][72]
        {
            const float4* src = (const float4*)(g_owtt + t * 2048);
            #pragma unroll
            for (int i = 0; i < 2; i++) {
                int q = tid + i * 128;               // 0..255 (16B = 8 halves)
                float4 v = src[q];
                *(float4*)(owt_h + (q >> 3) * 72 + (q & 7) * 8) = v;
            }
        }
        __syncthreads();

        const int base = (warp + t / 3) * 18 + (t % 3);
        #pragma unroll
        for (int s = 0; s < 4; s++) {
            const int ko = 16 * s + 2 * ti;
            const uint16_t* ap0 = patch + (base + g) * 72 + ko;
            const uint16_t* ap1 = patch + (base + g + 8) * 72 + ko;
            uint32_t a0 = *(const uint32_t*)ap0;
            uint32_t a2 = *(const uint32_t*)(ap0 + 8);
            uint32_t a1 = *(const uint32_t*)ap1;
            uint32_t a3 = *(const uint32_t*)(ap1 + 8);
            #pragma unroll
            for (int j = 0; j < 4; j++) {
                const uint16_t* bp = owt_h + (j * 8 + g) * 72 + ko;
                uint32_t b0 = *(const uint32_t*)bp;
                uint32_t b1 = *(const uint32_t*)(bp + 8);
                MMA_F16(aoff[j], a0, a1, a2, a3, b0, b1);
            }
        }
        __syncthreads();
    }

    // write raw_s[px][27] (+ offset bias); warp w owns px rows w*16+g, +8
    {
        const int r0 = warp * 16 + g, r1 = warp * 16 + 8 + g;
        #pragma unroll
        for (int j = 0; j < 4; j++) {
            int oc0 = 8 * j + 2 * ti;
            if (oc0 < NOFF) {
                float b = ob[oc0];
                raw_s[r0 * 28 + oc0] = aoff[j][0] + b;
                raw_s[r1 * 28 + oc0] = aoff[j][2] + b;
            }
            if (oc0 + 1 < NOFF) {
                float b = ob[oc0 + 1];
                raw_s[r0 * 28 + oc0 + 1] = aoff[j][1] + b;
                raw_s[r1 * 28 + oc0 + 1] = aoff[j][3] + b;
            }
        }
    }
    __syncthreads();

    // precompute (py, px, mask) for all 9 taps
    if (tid < 64) {
        const int y = tid >> 4, wxl = tid & 15;
        const int ho = ho0 + y, wo = wo0 + wxl;
        #pragma unroll
        for (int t = 0; t < 9; t++) {
            float dyv = raw_s[tid * 28 + 2 * t];
            float dxv = raw_s[tid * 28 + 2 * t + 1];
            float mv  = raw_s[tid * 28 + 18 + t];
            float m = 1.f / (1.f + expf(-mv));
            float* pp = pym + (t * 64 + tid) * 3;
            pp[0] = dyv + (float)(ho - 1 + t / 3);
            pp[1] = dxv + (float)(wo - 1 + t % 3);
            pp[2] = m;
        }
    }
    __syncthreads();

    // ======================= PHASE 2: main conv ============================
    const int sub = lane >> 3;                  // 0..3 (4 px per pass)
    const int c8 = (lane & 7) * 8;              // 8 channels per lane
    const int px0 = (warp & 1) * 32;
    const int o0  = (warp >> 1) * 32;
    const uint32_t val_b = smem_u32(val_h);
    const uint32_t w_b   = smem_u32(w_h);

    float acc[2][4][4];
    #pragma unroll
    for (int mt = 0; mt < 2; mt++)
        #pragma unroll
        for (int j = 0; j < 4; j++)
            #pragma unroll
            for (int i = 0; i < 4; i++) acc[mt][j][i] = 0.f;

    for (int t = 0; t < 9; t++) {
        // ---- stage AB: weights copy + gather (single buffer) ----
        {
            const float4* wsrc = (const float4*)(g_wtt + t * 4096);
            #pragma unroll
            for (int i = 0; i < 4; i++) {
                int q = tid + i * 128;               // 0..511 (16B = 8 halves)
                float4 v = wsrc[q];
                *(float4*)(w_h + (q >> 3) * 72 + (q & 7) * 8) = v;
            }
        }
        #pragma unroll
        for (int it = 0; it < 4; it++) {
            int px = warp * 16 + it * 4 + sub;       // 0..63
            const float* pp = pym + (t * 64 + px) * 3;
            float py = pp[0], pxx = pp[1], m = pp[2];
            float y0f = floorf(py), x0f = floorf(pxx);
            float wy1 = py - y0f, wy0 = 1.f - wy1;
            float wx1 = pxx - x0f, wx0 = 1.f - wx1;
            int y0 = (int)y0f, x0 = (int)x0f;
            int y1 = y0 + 1, x1 = x0 + 1;
            bool vy0 = (y0 >= 0) && (y0 < H), vy1 = (y1 >= 0) && (y1 < H);
            bool vx0 = (x0 >= 0) && (x0 < W), vx1 = (x1 >= 0) && (x1 < W);
            float w00 = (vy0 && vx0) ? wy0 * wx0 * m : 0.f;
            float w01 = (vy0 && vx1) ? wy0 * wx1 * m : 0.f;
            float w10 = (vy1 && vx0) ? wy1 * wx0 * m : 0.f;
            float w11 = (vy1 && vx1) ? wy1 * wx1 * m : 0.f;
            int yc0 = min(max(y0, 0), H - 1), yc1 = min(max(y1, 0), H - 1);
            int xc0 = min(max(x0, 0), W - 1), xc1 = min(max(x1, 0), W - 1);
            int i0 = yc0 * W + xc0, i1 = yc0 * W + xc1;
            int i2 = yc1 * W + xc0, i3 = yc1 * W + xc1;
            uint4 q0 = *(const uint4*)(xtn + (size_t)i0 * CIN + c8);
            uint4 q1 = *(const uint4*)(xtn + (size_t)i1 * CIN + c8);
            uint4 q2 = *(const uint4*)(xtn + (size_t)i2 * CIN + c8);
            uint4 q3 = *(const uint4*)(xtn + (size_t)i3 * CIN + c8);
            uint4 r;
            uint32_t* rp = (uint32_t*)&r;
            const uint32_t* p0 = (const uint32_t*)&q0;
            const uint32_t* p1 = (const uint32_t*)&q1;
            const uint32_t* p2 = (const uint32_t*)&q2;
            const uint32_t* p3 = (const uint32_t*)&q3;
            #pragma unroll
            for (int j = 0; j < 4; j++) {
                float2 a = __half22float2(*(const __half2*)&p0[j]);
                float2 b = __half22float2(*(const __half2*)&p1[j]);
                float2 c = __half22float2(*(const __half2*)&p2[j]);
                float2 d = __half22float2(*(const __half2*)&p3[j]);
                float vx = fmaf(w11, d.x, fmaf(w10, c.x, fmaf(w01, b.x, w00 * a.x)));
                float vy = fmaf(w11, d.y, fmaf(w10, c.y, fmaf(w01, b.y, w00 * a.y)));
                rp[j] = f2h2(vx, vy);
            }
            *(uint4*)(val_h + px * 72 + c8) = r;
        }
        __syncthreads();

        // ---- stage C: ldmatrix + m16n8k16 mma, warp tile 32 px x 32 o ----
        #pragma unroll
        for (int s = 0; s < 4; s++) {
            const int ko = 16 * s;
            uint32_t a[2][4];
            #pragma unroll
            for (int mt = 0; mt < 2; mt++) {
                uint32_t aaddr = val_b +
                    (uint32_t)(((px0 + 16 * mt + a_row) * 72 + ko + a_col) << 1);
                LDSM_X4(a[mt][0], a[mt][1], a[mt][2], a[mt][3], aaddr);
            }
            #pragma unroll
            for (int jp = 0; jp < 2; jp++) {
                uint32_t baddr = w_b +
                    (uint32_t)(((o0 + 16 * jp + b_row) * 72 + ko + b_col) << 1);
                uint32_t b0, b1, b2, b3;
                LDSM_X4(b0, b1, b2, b3, baddr);
                #pragma unroll
                for (int mt = 0; mt < 2; mt++) {
                    MMA_F16(acc[mt][2 * jp],     a[mt][0], a[mt][1], a[mt][2], a[mt][3], b0, b1);
                    MMA_F16(acc[mt][2 * jp + 1], a[mt][0], a[mt][1], a[mt][2], a[mt][3], b2, b3);
                }
            }
        }
        __syncthreads();
    }

    // ---- epilogue: D frags + bias -> out (NCHW) ----
    #pragma unroll
    for (int mt = 0; mt < 2; mt++) {
        const int ho = ho0 + 2 * (warp & 1) + mt;
        float* op = out + (((size_t)n * OUTC) * H + ho) * W + wo0;
        #pragma unroll
        for (int j = 0; j < 4; j++) {
            int oc = o0 + 8 * j + 2 * ti;
            float b0v = bs[oc], b1v = bs[oc + 1];
            op[(size_t)oc * HW + g]            = acc[mt][j][0] + b0v;
            op[(size_t)(oc + 1) * HW + g]      = acc[mt][j][1] + b1v;
            op[(size_t)oc * HW + g + 8]        = acc[mt][j][2] + b0v;
            op[(size_t)(oc + 1) * HW + g + 8]  = acc[mt][j][3] + b1v;
        }
    }
}

// ---------------------------------------------------------------------------
extern "C" void kernel_launch(void* const* d_in, const int* in_sizes, int n_in,
                              void* d_out, int out_size) {
    (void)in_sizes; (void)n_in; (void)out_size;
    const float* x        = (const float*)d_in[0];
    const float* weight   = (const float*)d_in[1];
    const float* bias     = (const float*)d_in[2];
    const float* offset_w = (const float*)d_in[3];
    const float* offset_b = (const float*)d_in[4];
    float* out = (float*)d_out;

    k_prep<<<3280, 256>>>(x, weight, offset_w);
    k_main<<<dim3(7, 28, 8), 128, 37376>>>(bias, offset_b, out);
}

// round 15
// speedup vs baseline: 1.2173x; 1.1042x over previous
#include <cuda_runtime.h>
#include <cuda_fp16.h>
#include <math.h>
#include <stdint.h>

// Problem constants (fixed shapes from reference)
#define H 112
#define W 112
#define HW 12544
#define CIN 64
#define OUTC 64
#define NB 8
#define NOFF 27          // 3*K*K
#define KK 576           // CIN * 9

// Scratch (static __device__ — no runtime allocation)
__device__ __align__(16) uint16_t g_xt[NB * HW * CIN];   // x in NHWC fp16 [N][H][W][C]
__device__ __align__(16) uint2 g_wf[9 * 8 * 4 * 32];     // main B frags [t][og][s][lane]
__device__ __align__(16) uint2 g_owf[9 * 4 * 4 * 32];    // offset B frags [t][og][s][lane]

#define MMA_F16(d, a0, a1, a2, a3, b0, b1)                                    \
    asm volatile("mma.sync.aligned.m16n8k16.row.col.f32.f16.f16.f32 "         \
        "{%0,%1,%2,%3}, {%4,%5,%6,%7}, {%8,%9}, {%0,%1,%2,%3};"               \
        : "+f"((d)[0]), "+f"((d)[1]), "+f"((d)[2]), "+f"((d)[3])              \
        : "r"(a0), "r"(a1), "r"(a2), "r"(a3), "r"(b0), "r"(b1))

#define LDSM_X4(r0, r1, r2, r3, a)                                            \
    asm volatile("ldmatrix.sync.aligned.m8n8.x4.shared.b16 {%0,%1,%2,%3}, [%4];" \
        : "=r"(r0), "=r"(r1), "=r"(r2), "=r"(r3) : "r"(a))

// pack 2 floats -> half2 bits
__device__ __forceinline__ uint32_t f2h2(float lo, float hi) {
    __half2 h = __floats2half2_rn(lo, hi);
    return *(uint32_t*)&h;
}
__device__ __forceinline__ uint32_t smem_u32(const void* p) {
    uint32_t a;
    asm("{ .reg .u64 t; cvta.to.shared.u64 t, %1; cvt.u32.u64 %0, t; }" : "=r"(a) : "l"(p));
    return a;
}

// ---------------------------------------------------------------------------
// Kernel 0 (merged prep): blocks [0,3136) NCHW f32 -> NHWC fp16;
//   blocks [3136,3280): weights -> fragment-ordered fp16 layouts.
// Frag mapping (m16n8k16 B, col-major): value w[o][c][t] lives at
//   g_wf[t][o>>3][c>>4][lane = (o&7)*4 + ((c&7)>>1)], half (((c>>3)&1)*2 + (c&1))
// ---------------------------------------------------------------------------
__global__ void k_prep(const float* __restrict__ x, const float* __restrict__ w,
                       const float* __restrict__ ow) {
    __shared__ float tile[64][33];
    const int bid = blockIdx.x, tid = threadIdx.x;
    if (bid < 3136) {
        const int n = bid / 392, p0 = (bid % 392) * 32;
        const float* xn = x + (size_t)n * CIN * HW;
        uint16_t* xtn = g_xt + (size_t)n * HW * CIN;
        const int tx = tid & 31, ty = tid >> 5;   // 32x8
        #pragma unroll
        for (int i = 0; i < 64; i += 8)
            tile[ty + i][tx] = xn[(size_t)(ty + i) * HW + p0 + tx];
        __syncthreads();
        const int p = tid >> 3, c8 = (tid & 7) * 8;
        uint4 u;
        u.x = f2h2(tile[c8 + 0][p], tile[c8 + 1][p]);
        u.y = f2h2(tile[c8 + 2][p], tile[c8 + 3][p]);
        u.z = f2h2(tile[c8 + 4][p], tile[c8 + 5][p]);
        u.w = f2h2(tile[c8 + 6][p], tile[c8 + 7][p]);
        *(uint4*)(xtn + (size_t)(p0 + p) * CIN + c8) = u;
    } else {
        int idx = (bid - 3136) * 256 + tid;       // 0..36863
        if (idx < 9 * 32 * 64) {                  // offset weights (oc pad 32)
            int t = idx >> 11, oc = (idx >> 6) & 31, c = idx & 63;
            float v = (oc < NOFF) ? ow[oc * KK + c * 9 + t] : 0.f;
            __half h = __float2half_rn(v);
            int lane = (oc & 7) * 4 + ((c & 7) >> 1);
            int hidx = ((((t * 4 + (oc >> 3)) * 4 + (c >> 4)) * 32 + lane) << 2)
                       + (((c >> 3) & 1) << 1) + (c & 1);
            ((uint16_t*)g_owf)[hidx] = *(uint16_t*)&h;
        }
        {                                         // main weights
            int t = idx >> 12, o = (idx >> 6) & 63, c = idx & 63;
            float v = w[o * KK + c * 9 + t];
            __half h = __float2half_rn(v);
            int lane = (o & 7) * 4 + ((c & 7) >> 1);
            int hidx = ((((t * 8 + (o >> 3)) * 4 + (c >> 4)) * 32 + lane) << 2)
                       + (((c >> 3) & 1) << 1) + (c & 1);
            ((uint16_t*)g_wf)[hidx] = *(uint16_t*)&h;
        }
    }
}

// ---------------------------------------------------------------------------
// Kernel 1 (fused): offset conv + deformable sampling + main GEMM.
// Tile: 16 wo x 4 ho = 64 px, 128 threads (4 warps), 7 CTAs/SM.
// B fragments (both convs) loaded DIRECTLY from fragment-ordered global
// (one coalesced LDG.64 per (j,s) per lane) — no smem staging, no B-LDSM.
//
// SMEM (29888 B):
//   [0    , 9216) val_h [64][72] h   | phase1: patch [108][72] h (15552,
//                                    |         spills past val region)
//   [15552,22720) raw_s [64][28] f32
//   [22720,29632) pym   [9][64][3] f32
//   [29632,29888) bs    [64] f32
// ---------------------------------------------------------------------------
__global__ void __launch_bounds__(128, 7)
k_main(const float* __restrict__ bias, const float* __restrict__ ob,
       float* __restrict__ out) {
    extern __shared__ unsigned char sm[];
    uint16_t* val_h = (uint16_t*)sm;                 // [64][72]
    uint16_t* patch = (uint16_t*)sm;                 // [108][72] (phase 1)
    float*    raw_s = (float*)(sm + 15552);          // [64][28]
    float*    pym   = (float*)(sm + 22720);          // [9][64][3]
    float*    bs    = (float*)(sm + 29632);          // [64]

    const int tid = threadIdx.x;
    const int wo0 = blockIdx.x * 16, ho0 = blockIdx.y * 4, n = blockIdx.z;
    const int lane = tid & 31, warp = tid >> 5;
    const uint16_t* xtn = g_xt + (size_t)n * (HW * CIN);

    // mma lane mapping
    const int g = lane >> 2, ti = lane & 3;
    // ldmatrix lane->address offsets (A side)
    const int a_row = lane & 15, a_col = (lane >> 4) << 3;

    if (tid >= 64) bs[tid - 64] = bias[tid - 64];

    // ======================= PHASE 1: offset conv ==========================
    for (int i = tid; i < 864; i += 128) {
        int pos = i >> 3, q8 = (i & 7) * 8;
        int gy = ho0 - 1 + pos / 18, gx = wo0 - 1 + pos % 18;
        uint4 u = make_uint4(0u, 0u, 0u, 0u);
        if (gy >= 0 && gy < H && gx >= 0 && gx < W)
            u = *(const uint4*)(xtn + (size_t)(gy * W + gx) * CIN + q8);
        *(uint4*)(patch + pos * 72 + q8) = u;
    }
    __syncthreads();     // patch ready; no further syncs in phase-1 loop

    float aoff[4][4];
    #pragma unroll
    for (int j = 0; j < 4; j++)
        #pragma unroll
        for (int i = 0; i < 4; i++) aoff[j][i] = 0.f;

    for (int t = 0; t < 9; t++) {
        const int base = (warp + t / 3) * 18 + (t % 3);
        #pragma unroll
        for (int s = 0; s < 4; s++) {
            const int ko = 16 * s + 2 * ti;
            const uint16_t* ap0 = patch + (base + g) * 72 + ko;
            const uint16_t* ap1 = patch + (base + g + 8) * 72 + ko;
            uint32_t a0 = *(const uint32_t*)ap0;
            uint32_t a2 = *(const uint32_t*)(ap0 + 8);
            uint32_t a1 = *(const uint32_t*)ap1;
            uint32_t a3 = *(const uint32_t*)(ap1 + 8);
            #pragma unroll
            for (int j = 0; j < 4; j++) {
                uint2 b = __ldg(g_owf + (((t * 4 + j) * 4 + s) << 5) + lane);
                MMA_F16(aoff[j], a0, a1, a2, a3, b.x, b.y);
            }
        }
    }

    // write raw_s[px][27] (+ offset bias); warp w owns px rows w*16+g, +8
    {
        const int r0 = warp * 16 + g, r1 = warp * 16 + 8 + g;
        #pragma unroll
        for (int j = 0; j < 4; j++) {
            int oc0 = 8 * j + 2 * ti;
            if (oc0 < NOFF) {
                float b = ob[oc0];
                raw_s[r0 * 28 + oc0] = aoff[j][0] + b;
                raw_s[r1 * 28 + oc0] = aoff[j][2] + b;
            }
            if (oc0 + 1 < NOFF) {
                float b = ob[oc0 + 1];
                raw_s[r0 * 28 + oc0 + 1] = aoff[j][1] + b;
                raw_s[r1 * 28 + oc0 + 1] = aoff[j][3] + b;
            }
        }
    }
    __syncthreads();

    // precompute (py, px, mask) for all 9 taps
    if (tid < 64) {
        const int y = tid >> 4, wxl = tid & 15;
        const int ho = ho0 + y, wo = wo0 + wxl;
        #pragma unroll
        for (int t = 0; t < 9; t++) {
            float dyv = raw_s[tid * 28 + 2 * t];
            float dxv = raw_s[tid * 28 + 2 * t + 1];
            float mv  = raw_s[tid * 28 + 18 + t];
            float m = 1.f / (1.f + expf(-mv));
            float* pp = pym + (t * 64 + tid) * 3;
            pp[0] = dyv + (float)(ho - 1 + t / 3);
            pp[1] = dxv + (float)(wo - 1 + t % 3);
            pp[2] = m;
        }
    }
    __syncthreads();

    // ======================= PHASE 2: main conv ============================
    const int sub = lane >> 3;                  // 0..3 (4 px per pass)
    const int c8 = (lane & 7) * 8;              // 8 channels per lane
    const int px0 = (warp & 1) * 32;
    const int o0  = (warp >> 1) * 32;
    const int ogb = o0 >> 3;
    const uint32_t val_b = smem_u32(val_h);

    float acc[2][4][4];
    #pragma unroll
    for (int mt = 0; mt < 2; mt++)
        #pragma unroll
        for (int j = 0; j < 4; j++)
            #pragma unroll
            for (int i = 0; i < 4; i++) acc[mt][j][i] = 0.f;

    for (int t = 0; t < 9; t++) {
        // ---- stage B: gather with inline corner math -> val_h ----
        #pragma unroll
        for (int it = 0; it < 4; it++) {
            int px = warp * 16 + it * 4 + sub;       // 0..63
            const float* pp = pym + (t * 64 + px) * 3;
            float py = pp[0], pxx = pp[1], m = pp[2];
            float y0f = floorf(py), x0f = floorf(pxx);
            float wy1 = py - y0f, wy0 = 1.f - wy1;
            float wx1 = pxx - x0f, wx0 = 1.f - wx1;
            int y0 = (int)y0f, x0 = (int)x0f;
            int y1 = y0 + 1, x1 = x0 + 1;
            bool vy0 = (y0 >= 0) && (y0 < H), vy1 = (y1 >= 0) && (y1 < H);
            bool vx0 = (x0 >= 0) && (x0 < W), vx1 = (x1 >= 0) && (x1 < W);
            float w00 = (vy0 && vx0) ? wy0 * wx0 * m : 0.f;
            float w01 = (vy0 && vx1) ? wy0 * wx1 * m : 0.f;
            float w10 = (vy1 && vx0) ? wy1 * wx0 * m : 0.f;
            float w11 = (vy1 && vx1) ? wy1 * wx1 * m : 0.f;
            int yc0 = min(max(y0, 0), H - 1), yc1 = min(max(y1, 0), H - 1);
            int xc0 = min(max(x0, 0), W - 1), xc1 = min(max(x1, 0), W - 1);
            int i0 = yc0 * W + xc0, i1 = yc0 * W + xc1;
            int i2 = yc1 * W + xc0, i3 = yc1 * W + xc1;
            uint4 q0 = *(const uint4*)(xtn + (size_t)i0 * CIN + c8);
            uint4 q1 = *(const uint4*)(xtn + (size_t)i1 * CIN + c8);
            uint4 q2 = *(const uint4*)(xtn + (size_t)i2 * CIN + c8);
            uint4 q3 = *(const uint4*)(xtn + (size_t)i3 * CIN + c8);
            uint4 r;
            uint32_t* rp = (uint32_t*)&r;
            const uint32_t* p0 = (const uint32_t*)&q0;
            const uint32_t* p1 = (const uint32_t*)&q1;
            const uint32_t* p2 = (const uint32_t*)&q2;
            const uint32_t* p3 = (const uint32_t*)&q3;
            #pragma unroll
            for (int j = 0; j < 4; j++) {
                float2 a = __half22float2(*(const __half2*)&p0[j]);
                float2 b = __half22float2(*(const __half2*)&p1[j]);
                float2 c = __half22float2(*(const __half2*)&p2[j]);
                float2 d = __half22float2(*(const __half2*)&p3[j]);
                float vx = fmaf(w11, d.x, fmaf(w10, c.x, fmaf(w01, b.x, w00 * a.x)));
                float vy = fmaf(w11, d.y, fmaf(w10, c.y, fmaf(w01, b.y, w00 * a.y)));
                rp[j] = f2h2(vx, vy);
            }
            *(uint4*)(val_h + px * 72 + c8) = r;
        }
        __syncthreads();

        // ---- stage C: A via ldmatrix, B via direct frag LDG ----
        #pragma unroll
        for (int s = 0; s < 4; s++) {
            uint32_t a[2][4];
            #pragma unroll
            for (int mt = 0; mt < 2; mt++) {
                uint32_t aaddr = val_b +
                    (uint32_t)(((px0 + 16 * mt + a_row) * 72 + 16 * s + a_col) << 1);
                LDSM_X4(a[mt][0], a[mt][1], a[mt][2], a[mt][3], aaddr);
            }
            #pragma unroll
            for (int j = 0; j < 4; j++) {
                uint2 b = __ldg(g_wf + (((t * 8 + ogb + j) * 4 + s) << 5) + lane);
                MMA_F16(acc[0][j], a[0][0], a[0][1], a[0][2], a[0][3], b.x, b.y);
                MMA_F16(acc[1][j], a[1][0], a[1][1], a[1][2], a[1][3], b.x, b.y);
            }
        }
        __syncthreads();
    }

    // ---- epilogue: D frags + bias -> out (NCHW) ----
    #pragma unroll
    for (int mt = 0; mt < 2; mt++) {
        const int ho = ho0 + 2 * (warp & 1) + mt;
        float* op = out + (((size_t)n * OUTC) * H + ho) * W + wo0;
        #pragma unroll
        for (int j = 0; j < 4; j++) {
            int oc = o0 + 8 * j + 2 * ti;
            float b0v = bs[oc], b1v = bs[oc + 1];
            op[(size_t)oc * HW + g]            = acc[mt][j][0] + b0v;
            op[(size_t)(oc + 1) * HW + g]      = acc[mt][j][1] + b1v;
            op[(size_t)oc * HW + g + 8]        = acc[mt][j][2] + b0v;
            op[(size_t)(oc + 1) * HW + g + 8]  = acc[mt][j][3] + b1v;
        }
    }
}

// ---------------------------------------------------------------------------
extern "C" void kernel_launch(void* const* d_in, const int* in_sizes, int n_in,
                              void* d_out, int out_size) {
    (void)in_sizes; (void)n_in; (void)out_size;
    const float* x        = (const float*)d_in[0];
    const float* weight   = (const float*)d_in[1];
    const float* bias     = (const float*)d_in[2];
    const float* offset_w = (const float*)d_in[3];
    const float* offset_b = (const float*)d_in[4];
    float* out = (float*)d_out;

    k_prep<<<3280, 256>>>(x, weight, offset_w);
    k_main<<<dim3(7, 28, 8), 128, 29888>>>(bias, offset_b, out);
}